// round 12
// baseline (speedup 1.0000x reference)
#include <cuda_runtime.h>
#include <cuda_bf16.h>

#define B_  8
#define H_  8
#define N_  512
#define K_  16
#define BN  (B_*N_)          // 4096
#define NN  (N_*N_)          // 262144

__device__ float g_A[BN * 256];     // per-(b,n) algebra element A, row-major 16x16
__device__ float g_V[BN * K_];      // v = exp(-A) mu
__device__ float g_bavg[B_ * NN];   // head-averaged beta (8 MB)

// ---------------------------------------------------------------------------
// Warp-collective: y = exp(A) x for a 16x16 A (M-term Taylor, Horner).
// Lane l owns row r = l&15 of A. x_own = component r of x (lanes 16-31 mirror).
// ---------------------------------------------------------------------------
template<int M>
__device__ __forceinline__ float exp_apply(const float Ar[16], float x_own) {
    float x[16], y[16];
    #pragma unroll
    for (int c = 0; c < 16; ++c) {
        x[c] = __shfl_sync(0xffffffffu, x_own, c);
        y[c] = x[c];
    }
    float y_own = x_own;
    #pragma unroll
    for (int k = M; k >= 1; --k) {
        float z0 = 0.0f, z1 = 0.0f;
        #pragma unroll
        for (int c = 0; c < 16; c += 2) {
            z0 += Ar[c]     * y[c];
            z1 += Ar[c + 1] * y[c + 1];
        }
        float zk = (z0 + z1) * (1.0f / (float)k);
        y_own = x_own + zk;
        #pragma unroll
        for (int c = 0; c < 16; ++c)
            y[c] = x[c] + __shfl_sync(0xffffffffu, zk, c);
    }
    return y_own;
}

// ---------------------------------------------------------------------------
// Kernel 0 (fused): blocks [0,2048) stream the beta head-average;
// blocks [2048,2560) do the per-(b,n) prep (A matrix + v = exp(-A) mu).
// ---------------------------------------------------------------------------
__global__ __launch_bounds__(256)
void fused_prep_kernel(const float* __restrict__ beta,
                       const float* __restrict__ mu,
                       const float* __restrict__ phi,
                       const float* __restrict__ gen) {
    if (blockIdx.x < 2048) {
        int m4 = blockIdx.x * 256 + threadIdx.x;   // float4 index, B_*NN/4 total
        int b  = m4 >> 16;                          // / (NN/4 = 65536)
        int r4 = m4 & 65535;
        const float4* src = (const float4*)beta + (size_t)b * (H_ * NN / 4) + r4;

        float4 v0 = src[0 * (NN/4)], v1 = src[1 * (NN/4)];
        float4 v2 = src[2 * (NN/4)], v3 = src[3 * (NN/4)];
        float4 v4 = src[4 * (NN/4)], v5 = src[5 * (NN/4)];
        float4 v6 = src[6 * (NN/4)], v7 = src[7 * (NN/4)];

        float4 s;
        s.x = (((v0.x + v1.x) + (v2.x + v3.x)) + ((v4.x + v5.x) + (v6.x + v7.x))) * 0.125f;
        s.y = (((v0.y + v1.y) + (v2.y + v3.y)) + ((v4.y + v5.y) + (v6.y + v7.y))) * 0.125f;
        s.z = (((v0.z + v1.z) + (v2.z + v3.z)) + ((v4.z + v5.z) + (v6.z + v7.z))) * 0.125f;
        s.w = (((v0.w + v1.w) + (v2.w + v3.w)) + ((v4.w + v5.w) + (v6.w + v7.w))) * 0.125f;

        ((float4*)g_bavg)[m4] = s;
    } else {
        int bid  = blockIdx.x - 2048;
        int w = threadIdx.x >> 5, lane = threadIdx.x & 31, r = lane & 15;
        int bn = bid * 8 + w;

        float p0 = phi[bn * 3 + 0], p1 = phi[bn * 3 + 1], p2 = phi[bn * 3 + 2];

        float Ar[16];
        const float4* g4 = (const float4*)gen;
        #pragma unroll
        for (int q = 0; q < 4; ++q) {
            float4 a = g4[(0 * 256 + r * 16) / 4 + q];
            float4 b = g4[(1 * 256 + r * 16) / 4 + q];
            float4 c = g4[(2 * 256 + r * 16) / 4 + q];
            Ar[4 * q + 0] = p0 * a.x + p1 * b.x + p2 * c.x;
            Ar[4 * q + 1] = p0 * a.y + p1 * b.y + p2 * c.y;
            Ar[4 * q + 2] = p0 * a.z + p1 * b.z + p2 * c.z;
            Ar[4 * q + 3] = p0 * a.w + p1 * b.w + p2 * c.w;
        }
        if (lane < 16) {
            float4* A4 = (float4*)(g_A + (size_t)bn * 256 + r * 16);
            #pragma unroll
            for (int q = 0; q < 4; ++q)
                A4[q] = make_float4(Ar[4*q], Ar[4*q+1], Ar[4*q+2], Ar[4*q+3]);
        }

        float nAr[16];
        #pragma unroll
        for (int c = 0; c < 16; ++c) nAr[c] = -Ar[c];

        float x_own = mu[bn * 16 + r];
        float v = exp_apply<16>(nAr, x_own);
        if (lane < 16) g_V[bn * 16 + lane] = v;
    }
}

// ---------------------------------------------------------------------------
// Kernel 1: warp-per-row main pass. Block = 8 warps = 8 rows of one batch.
// minBlocksPerMultiprocessor=3 -> 85 regs, 24 warps/SM, 1.15 waves.
// (R11 lesson: 90 regs silently dropped us to 2 blocks/SM; R5 lesson: don't
//  force below ~80 or spills eat the win.)
// ---------------------------------------------------------------------------
__global__ __launch_bounds__(256, 3)
void vffn_main_kernel(const float* __restrict__ mu,
                      const float* __restrict__ mu_prior,
                      const float* __restrict__ lr_ptr,
                      float* __restrict__ out) {
    __shared__ float Vs[N_ * 20];
    __shared__ float qs[N_];
    __shared__ float cbs[8 * N_];      // 8 rows x 512 cb values

    int t = threadIdx.x, lane = t & 31, w = t >> 5, r = lane & 15;
    int b = blockIdx.x >> 6;                 // 64 blocks per batch
    int i0 = (blockIdx.x & 63) << 3;
    int i = i0 + w;                          // this warp's row
    int bn = b * N_ + i;
    float lr = *lr_ptr;

    // Stage V[b] into padded smem (stride 20 floats; float4-aligned)
    const float4* V4 = (const float4*)(g_V + (size_t)b * N_ * K_);
    for (int idx = t; idx < N_ * 4; idx += 256) {
        int j = idx >> 2, q = idx & 3;
        ((float4*)(Vs + j * 20))[q] = V4[j * 4 + q];
    }
    // Stage this block's 8 bavg rows (contiguous 16 KB, coalesced float4)
    {
        const float4* ba4 = (const float4*)(g_bavg + (size_t)b * NN + (size_t)i0 * N_);
        float4* cb4 = (float4*)cbs;
        #pragma unroll
        for (int q = 0; q < 4; ++q)
            cb4[t + 256 * q] = ba4[t + 256 * q];
    }
    __syncthreads();
    for (int j = t; j < N_; j += 256) {
        float q = 0.0f;
        #pragma unroll
        for (int k = 0; k < 16; ++k) { float v = Vs[j * 20 + k]; q += v * v; }
        qs[j] = q;
    }
    __syncthreads();

    float vi[16];
    #pragma unroll
    for (int q = 0; q < 4; ++q) {
        float4 v4 = ((const float4*)(Vs + i * 20))[q];
        vi[4*q] = v4.x; vi[4*q+1] = v4.y; vi[4*q+2] = v4.z; vi[4*q+3] = v4.w;
    }
    float qi = qs[i];

    float S0 = 0.0f, sac = 0.0f;
    float u[32];                          // u[0..15]=Sv, u[16..31]=Tv
    #pragma unroll
    for (int k = 0; k < 32; ++k) u[k] = 0.0f;

    const float* cbrow = cbs + w * N_;

    #pragma unroll 4
    for (int jj = 0; jj < 16; ++jj) {
        int j = lane + 32 * jj;
        float cb = cbrow[j];                 // lane-stride-1, conflict-free LDS

        float vj[16];
        #pragma unroll
        for (int q = 0; q < 4; ++q) {
            float4 uu = ((const float4*)(Vs + j * 20))[q];
            vj[4*q] = uu.x; vj[4*q+1] = uu.y; vj[4*q+2] = uu.z; vj[4*q+3] = uu.w;
        }
        float d0 = 0.0f, d1 = 0.0f;
        #pragma unroll
        for (int k = 0; k < 16; k += 2) { d0 += vi[k]*vj[k]; d1 += vi[k+1]*vj[k+1]; }
        float kl  = 0.5f * (qi + qs[j]) - (d0 + d1);   // / TAU = 1
        float wgt = cb * kl;
        S0  += cb;
        sac += wgt;
        #pragma unroll
        for (int k = 0; k < 16; ++k) {
            u[k]      += cb  * vj[k];
            u[16 + k] += wgt * vj[k];
        }
    }

    // ---- recursive-halving reduce-scatter of u[32]: 31 SHFL total.
    {
        bool hi = (lane & 16) != 0;
        #pragma unroll
        for (int k = 0; k < 16; ++k) {
            float send = hi ? u[k] : u[k + 16];
            float keep = hi ? u[k + 16] : u[k];
            u[k] = keep + __shfl_xor_sync(0xffffffffu, send, 16);
        }
        hi = (lane & 8) != 0;
        #pragma unroll
        for (int k = 0; k < 8; ++k) {
            float send = hi ? u[k] : u[k + 8];
            float keep = hi ? u[k + 8] : u[k];
            u[k] = keep + __shfl_xor_sync(0xffffffffu, send, 8);
        }
        hi = (lane & 4) != 0;
        #pragma unroll
        for (int k = 0; k < 4; ++k) {
            float send = hi ? u[k] : u[k + 4];
            float keep = hi ? u[k + 4] : u[k];
            u[k] = keep + __shfl_xor_sync(0xffffffffu, send, 4);
        }
        hi = (lane & 2) != 0;
        #pragma unroll
        for (int k = 0; k < 2; ++k) {
            float send = hi ? u[k] : u[k + 2];
            float keep = hi ? u[k + 2] : u[k];
            u[k] = keep + __shfl_xor_sync(0xffffffffu, send, 2);
        }
        hi = (lane & 1) != 0;
        {
            float send = hi ? u[0] : u[1];
            float keep = hi ? u[1] : u[0];
            u[0] = keep + __shfl_xor_sync(0xffffffffu, send, 1);
        }
    }
    // lane l (<16): u[0] = Sv[l]; lane l (>=16): u[0] = Tv[l-16]. Swap halves:
    float other = __shfl_xor_sync(0xffffffffu, u[0], 16);
    float Sv_f = (lane < 16) ? u[0] : other;
    float Tv_f = (lane < 16) ? other : u[0];

    // S0 / sac full butterfly (10 SHFL)
    #pragma unroll
    for (int off = 16; off > 0; off >>= 1) {
        S0  += __shfl_xor_sync(0xffffffffu, S0,  off);
        sac += __shfl_xor_sync(0xffffffffu, sac, off);
    }

    // rv component r, naturally distributed (lane r holds rv[r])
    float vik = vi[r];
    float rv_own = (S0 * vik - Sv_f)
                 + (sac * (1.0f - S0) * vik + sac * Sv_f - Tv_f);

    // Rotation grad = exp(A) rv
    float Ar[16];
    const float4* A4 = (const float4*)(g_A + (size_t)bn * 256 + r * 16);
    #pragma unroll
    for (int q = 0; q < 4; ++q) {
        float4 a = A4[q];
        Ar[4*q] = a.x; Ar[4*q+1] = a.y; Ar[4*q+2] = a.z; Ar[4*q+3] = a.w;
    }
    float grad = exp_apply<8>(Ar, rv_own);

    if (lane < 16) {
        float m  = mu[bn * 16 + lane];
        float mp = mu_prior[bn * 16 + lane];
        out[bn * 16 + lane] = m - lr * (0.001f * (m - mp) + grad);
    }
}

// ---------------------------------------------------------------------------
extern "C" void kernel_launch(void* const* d_in, const int* in_sizes, int n_in,
                              void* d_out, int out_size) {
    const float* mu       = (const float*)d_in[0];
    const float* beta     = (const float*)d_in[1];
    const float* mu_prior = (const float*)d_in[2];
    const float* phi      = (const float*)d_in[3];
    const float* gen      = (const float*)d_in[4];
    const float* lr       = (const float*)d_in[5];
    float* out = (float*)d_out;

    fused_prep_kernel<<<2048 + BN / 8, 256>>>(beta, mu, phi, gen);
    vffn_main_kernel<<<BN / 8, 256>>>(mu, mu_prior, lr, out);
}

// round 13
// speedup vs baseline: 1.1856x; 1.1856x over previous
#include <cuda_runtime.h>
#include <cuda_bf16.h>

#define B_  8
#define H_  8
#define N_  512
#define K_  16
#define BN  (B_*N_)          // 4096
#define NN  (N_*N_)          // 262144

__device__ float g_A[BN * 256];     // per-(b,n) algebra element A, row-major 16x16
__device__ float g_V[BN * K_];      // v = exp(-A) mu

// ---------------------------------------------------------------------------
// Warp-collective: y = exp(A) x for a 16x16 A (M-term Taylor, Horner).
// Lane l owns row r = l&15 of A. x_own = component r of x (lanes 16-31 mirror).
// ---------------------------------------------------------------------------
template<int M>
__device__ __forceinline__ float exp_apply(const float Ar[16], float x_own) {
    float x[16], y[16];
    #pragma unroll
    for (int c = 0; c < 16; ++c) {
        x[c] = __shfl_sync(0xffffffffu, x_own, c);
        y[c] = x[c];
    }
    float y_own = x_own;
    #pragma unroll
    for (int k = M; k >= 1; --k) {
        float z0 = 0.0f, z1 = 0.0f;
        #pragma unroll
        for (int c = 0; c < 16; c += 2) {
            z0 += Ar[c]     * y[c];
            z1 += Ar[c + 1] * y[c + 1];
        }
        float zk = (z0 + z1) * (1.0f / (float)k);
        y_own = x_own + zk;
        #pragma unroll
        for (int c = 0; c < 16; ++c)
            y[c] = x[c] + __shfl_sync(0xffffffffu, zk, c);
    }
    return y_own;
}

// ---------------------------------------------------------------------------
// Kernel 0: per (b,n): A = sum_g phi_g G_g (store), v = exp(-A) mu (store).
// ---------------------------------------------------------------------------
__global__ __launch_bounds__(256)
void prep_kernel(const float* __restrict__ mu,
                 const float* __restrict__ phi,
                 const float* __restrict__ gen) {
    int w = threadIdx.x >> 5, lane = threadIdx.x & 31, r = lane & 15;
    int bn = blockIdx.x * 8 + w;

    float p0 = phi[bn * 3 + 0], p1 = phi[bn * 3 + 1], p2 = phi[bn * 3 + 2];

    float Ar[16];
    const float4* g4 = (const float4*)gen;
    #pragma unroll
    for (int q = 0; q < 4; ++q) {
        float4 a = g4[(0 * 256 + r * 16) / 4 + q];
        float4 b = g4[(1 * 256 + r * 16) / 4 + q];
        float4 c = g4[(2 * 256 + r * 16) / 4 + q];
        Ar[4 * q + 0] = p0 * a.x + p1 * b.x + p2 * c.x;
        Ar[4 * q + 1] = p0 * a.y + p1 * b.y + p2 * c.y;
        Ar[4 * q + 2] = p0 * a.z + p1 * b.z + p2 * c.z;
        Ar[4 * q + 3] = p0 * a.w + p1 * b.w + p2 * c.w;
    }
    if (lane < 16) {
        float4* A4 = (float4*)(g_A + (size_t)bn * 256 + r * 16);
        #pragma unroll
        for (int q = 0; q < 4; ++q)
            A4[q] = make_float4(Ar[4*q], Ar[4*q+1], Ar[4*q+2], Ar[4*q+3]);
    }

    float nAr[16];
    #pragma unroll
    for (int c = 0; c < 16; ++c) nAr[c] = -Ar[c];

    float x_own = mu[bn * 16 + r];
    float v = exp_apply<16>(nAr, x_own);
    if (lane < 16) g_V[bn * 16 + lane] = v;
}

// ---------------------------------------------------------------------------
// Kernel 1: fused stream+compute. Block = 8 warps = 8 rows of one batch.
// Phase A: block streams its OWN beta slice (8 rows x 8 heads = 64 KB) with
//   head-sum into cbs (16 KB smem) — the havg kernel inlined per block.
//   Resident-neighbor blocks' compute overlaps this DRAM stream.
// Phase B: R12's proven loop (Vs stride-20 conflict-free, j=lane+32*jj),
//   reduce-scatter epilogue, exp(A) rotation, update.
// ---------------------------------------------------------------------------
__global__ __launch_bounds__(256)
void vffn_main_kernel(const float* __restrict__ beta,
                      const float* __restrict__ mu,
                      const float* __restrict__ mu_prior,
                      const float* __restrict__ lr_ptr,
                      float* __restrict__ out) {
    __shared__ float Vs[N_ * 20];
    __shared__ float qs[N_];
    __shared__ float cbs[8 * N_];      // 8 rows x 512 head-avg values

    int t = threadIdx.x, lane = t & 31, w = t >> 5, r = lane & 15;
    int b = blockIdx.x >> 6;                 // 64 blocks per batch
    int i0 = (blockIdx.x & 63) << 3;
    int i = i0 + w;                          // this warp's row
    int bn = b * N_ + i;
    float lr = *lr_ptr;

    // ---- Phase A: stream beta rows [i0,i0+8) over all 8 heads, head-summed.
    // 8 independent LDG.128 per step, 4 steps/thread: deep MLP.
    {
        const float4* bb4 = (const float4*)(beta + (size_t)b * H_ * NN + (size_t)i0 * N_);
        const int HS = NN / 4;               // float4 stride between heads
        float4* cb4 = (float4*)cbs;
        #pragma unroll
        for (int s0 = 0; s0 < 1024; s0 += 256) {
            int s = s0 + t;
            float4 h0 = bb4[s + 0*HS], h1 = bb4[s + 1*HS];
            float4 h2 = bb4[s + 2*HS], h3 = bb4[s + 3*HS];
            float4 h4 = bb4[s + 4*HS], h5 = bb4[s + 5*HS];
            float4 h6 = bb4[s + 6*HS], h7 = bb4[s + 7*HS];
            float4 o;
            o.x = (((h0.x+h1.x)+(h2.x+h3.x))+((h4.x+h5.x)+(h6.x+h7.x)))*0.125f;
            o.y = (((h0.y+h1.y)+(h2.y+h3.y))+((h4.y+h5.y)+(h6.y+h7.y)))*0.125f;
            o.z = (((h0.z+h1.z)+(h2.z+h3.z))+((h4.z+h5.z)+(h6.z+h7.z)))*0.125f;
            o.w = (((h0.w+h1.w)+(h2.w+h3.w))+((h4.w+h5.w)+(h6.w+h7.w)))*0.125f;
            cb4[s] = o;
        }
    }
    // Stage V[b] into padded smem (stride 20 floats; float4-aligned)
    const float4* V4 = (const float4*)(g_V + (size_t)b * N_ * K_);
    for (int idx = t; idx < N_ * 4; idx += 256) {
        int j = idx >> 2, q = idx & 3;
        ((float4*)(Vs + j * 20))[q] = V4[idx];
    }
    __syncthreads();
    for (int j = t; j < N_; j += 256) {
        float q = 0.0f;
        #pragma unroll
        for (int k = 0; k < 16; ++k) { float v = Vs[j * 20 + k]; q += v * v; }
        qs[j] = q;
    }
    __syncthreads();

    // ---- Phase B: per-row reduction over j.
    float vi[16];
    #pragma unroll
    for (int q = 0; q < 4; ++q) {
        float4 v4 = ((const float4*)(Vs + i * 20))[q];
        vi[4*q] = v4.x; vi[4*q+1] = v4.y; vi[4*q+2] = v4.z; vi[4*q+3] = v4.w;
    }
    float qi = qs[i];

    float S0 = 0.0f, sac = 0.0f;
    float u[32];                          // u[0..15]=Sv, u[16..31]=Tv
    #pragma unroll
    for (int k = 0; k < 32; ++k) u[k] = 0.0f;

    const float* cbrow = cbs + w * N_;

    #pragma unroll 4
    for (int jj = 0; jj < 16; ++jj) {
        int j = lane + 32 * jj;
        float cb = cbrow[j];                 // lane-stride-1, conflict-free LDS

        float vj[16];
        #pragma unroll
        for (int q = 0; q < 4; ++q) {
            float4 uu = ((const float4*)(Vs + j * 20))[q];
            vj[4*q] = uu.x; vj[4*q+1] = uu.y; vj[4*q+2] = uu.z; vj[4*q+3] = uu.w;
        }
        float d0 = 0.0f, d1 = 0.0f;
        #pragma unroll
        for (int k = 0; k < 16; k += 2) { d0 += vi[k]*vj[k]; d1 += vi[k+1]*vj[k+1]; }
        float kl  = 0.5f * (qi + qs[j]) - (d0 + d1);   // / TAU = 1
        float wgt = cb * kl;
        S0  += cb;
        sac += wgt;
        #pragma unroll
        for (int k = 0; k < 16; ++k) {
            u[k]      += cb  * vj[k];
            u[16 + k] += wgt * vj[k];
        }
    }

    // ---- recursive-halving reduce-scatter of u[32]: 31 SHFL total.
    {
        bool hi = (lane & 16) != 0;
        #pragma unroll
        for (int k = 0; k < 16; ++k) {
            float send = hi ? u[k] : u[k + 16];
            float keep = hi ? u[k + 16] : u[k];
            u[k] = keep + __shfl_xor_sync(0xffffffffu, send, 16);
        }
        hi = (lane & 8) != 0;
        #pragma unroll
        for (int k = 0; k < 8; ++k) {
            float send = hi ? u[k] : u[k + 8];
            float keep = hi ? u[k + 8] : u[k];
            u[k] = keep + __shfl_xor_sync(0xffffffffu, send, 8);
        }
        hi = (lane & 4) != 0;
        #pragma unroll
        for (int k = 0; k < 4; ++k) {
            float send = hi ? u[k] : u[k + 4];
            float keep = hi ? u[k + 4] : u[k];
            u[k] = keep + __shfl_xor_sync(0xffffffffu, send, 4);
        }
        hi = (lane & 2) != 0;
        #pragma unroll
        for (int k = 0; k < 2; ++k) {
            float send = hi ? u[k] : u[k + 2];
            float keep = hi ? u[k + 2] : u[k];
            u[k] = keep + __shfl_xor_sync(0xffffffffu, send, 2);
        }
        hi = (lane & 1) != 0;
        {
            float send = hi ? u[0] : u[1];
            float keep = hi ? u[1] : u[0];
            u[0] = keep + __shfl_xor_sync(0xffffffffu, send, 1);
        }
    }
    // lane l (<16): u[0] = Sv[l]; lane l (>=16): u[0] = Tv[l-16]. Swap halves:
    float other = __shfl_xor_sync(0xffffffffu, u[0], 16);
    float Sv_f = (lane < 16) ? u[0] : other;
    float Tv_f = (lane < 16) ? other : u[0];

    // S0 / sac full butterfly (10 SHFL)
    #pragma unroll
    for (int off = 16; off > 0; off >>= 1) {
        S0  += __shfl_xor_sync(0xffffffffu, S0,  off);
        sac += __shfl_xor_sync(0xffffffffu, sac, off);
    }

    // rv component r, naturally distributed (lane r holds rv[r])
    float vik = vi[r];
    float rv_own = (S0 * vik - Sv_f)
                 + (sac * (1.0f - S0) * vik + sac * Sv_f - Tv_f);

    // Rotation grad = exp(A) rv
    float Ar[16];
    const float4* A4 = (const float4*)(g_A + (size_t)bn * 256 + r * 16);
    #pragma unroll
    for (int q = 0; q < 4; ++q) {
        float4 a = A4[q];
        Ar[4*q] = a.x; Ar[4*q+1] = a.y; Ar[4*q+2] = a.z; Ar[4*q+3] = a.w;
    }
    float grad = exp_apply<8>(Ar, rv_own);

    if (lane < 16) {
        float m  = mu[bn * 16 + lane];
        float mp = mu_prior[bn * 16 + lane];
        out[bn * 16 + lane] = m - lr * (0.001f * (m - mp) + grad);
    }
}

// ---------------------------------------------------------------------------
extern "C" void kernel_launch(void* const* d_in, const int* in_sizes, int n_in,
                              void* d_out, int out_size) {
    const float* mu       = (const float*)d_in[0];
    const float* beta     = (const float*)d_in[1];
    const float* mu_prior = (const float*)d_in[2];
    const float* phi      = (const float*)d_in[3];
    const float* gen      = (const float*)d_in[4];
    const float* lr       = (const float*)d_in[5];
    float* out = (float*)d_out;

    prep_kernel<<<BN / 8, 256>>>(mu, phi, gen);
    vffn_main_kernel<<<BN / 8, 256>>>(beta, mu, mu_prior, lr, out);
}